// round 2
// baseline (speedup 1.0000x reference)
#include <cuda_runtime.h>

// DBTransformerLayer fused kernel, fp32 SIMT baseline.
//
// Pipeline per relation r (rel0: A->B edges eAB, updates out_B; rel1: B->A, updates out_A):
//   per block of EB=8 edges (one CTA):
//     gather x_i (dst tokens) and x_src; x_j = x_src @ bw^T + bb
//     Xc[8 edges][8 tokens][128]  (tokens 0..3 = x_i, 4..7 = x_j)
//     QKV = Xc @ Wi^T + bi ; per-(edge,head) 8x8 softmax attention -> O
//     X1 = LN1(Xc + O @ Wo^T + bo)
//     Y  = LN2(X1 + relu(X1 @ W1^T + b1) @ W2^T + b2)
//     atomicAdd Y tokens 0..3 into out[dst]
//   then divide by per-dst edge counts (scatter-mean).

#define EB   8
#define NTH  256

__device__ int g_cnt[40960];   // [0..NA): A-node counts, [NA..NA+NB): B-node counts

// smem layout (floats)
constexpr int S_XC = 0;          // 64 x 128
constexpr int S_Q  = 8192;       // 64 x 128
constexpr int S_K  = 16384;      // 64 x 128 (reused as FF hidden 64x64)
constexpr int S_V  = 24576;      // 64 x 128
constexpr int S_O  = 32768;      // 64 x 128 (also src staging 32x128, also final Y)
constexpr int S_W  = 40960;      // weight staging, k-major [K up to 128][68]
constexpr int S_FLOATS = S_W + 128*68;            // 49664
constexpr size_t SMEM_BYTES = (size_t)S_FLOATS*4 + 64;  // + edge index area

// C[M x N] = A[M x K] @ Wg[N x K]^T (+bias) (+Res) (relu) ; A,C,Res in smem, Wg/bias global.
// MODE: 0 = plain, 1 = relu, 2 = +Res.  REMAP maps b_proj rows (e*4+t) -> Xc rows (e*8+4+t).
template<int K, int MT, int MODE, bool REMAP>
__device__ __forceinline__ void gemm(
    const float* __restrict__ A, const float* __restrict__ Wg,
    const float* __restrict__ bias, int N, float* __restrict__ C, int ldc,
    const float* __restrict__ Res, float* __restrict__ wb, int tid)
{
    const int tx = tid & 15, ty = tid >> 4;
    for (int n0 = 0; n0 < N; n0 += 64) {
        // stage 64 W rows, transposed to k-major [k][68] (lane-contiguous STS: conflict-free)
        const int tot = 64 * (K / 4);
        for (int i = tid; i < tot; i += NTH) {
            int n = i & 63, kq = i >> 6;
            float4 g4 = *(const float4*)(Wg + (size_t)(n0 + n) * K + kq * 4);
            wb[(kq*4 + 0)*68 + n] = g4.x;
            wb[(kq*4 + 1)*68 + n] = g4.y;
            wb[(kq*4 + 2)*68 + n] = g4.z;
            wb[(kq*4 + 3)*68 + n] = g4.w;
        }
        __syncthreads();

        float acc[MT][4];
        #pragma unroll
        for (int i = 0; i < MT; i++) { acc[i][0]=0.f; acc[i][1]=0.f; acc[i][2]=0.f; acc[i][3]=0.f; }

        #pragma unroll 2
        for (int k = 0; k < K; k += 4) {
            float wf[4][4];
            *(float4*)wf[0] = *(const float4*)(wb + (k+0)*68 + tx*4);
            *(float4*)wf[1] = *(const float4*)(wb + (k+1)*68 + tx*4);
            *(float4*)wf[2] = *(const float4*)(wb + (k+2)*68 + tx*4);
            *(float4*)wf[3] = *(const float4*)(wb + (k+3)*68 + tx*4);
            // hoist all A fragments for this k-quad before the FMA block so ptxas
            // can batch the LDS.128s and cover LDS latency with independent FMAs
            float af[MT][4];
            #pragma unroll
            for (int i = 0; i < MT; i++)
                *(float4*)af[i] = *(const float4*)(A + (ty*MT + i)*K + k);
            #pragma unroll
            for (int i = 0; i < MT; i++) {
                #pragma unroll
                for (int j = 0; j < 4; j++)
                    acc[i][j] += af[i][0]*wf[0][j] + af[i][1]*wf[1][j]
                               + af[i][2]*wf[2][j] + af[i][3]*wf[3][j];
            }
        }

        float4 bv = *(const float4*)(bias + n0 + tx*4);
        #pragma unroll
        for (int i = 0; i < MT; i++) {
            int row = ty*MT + i;
            float4 o;
            o.x = acc[i][0] + bv.x; o.y = acc[i][1] + bv.y;
            o.z = acc[i][2] + bv.z; o.w = acc[i][3] + bv.w;
            if (MODE == 2) {
                float4 r4 = *(const float4*)(Res + row*128 + n0 + tx*4);
                o.x += r4.x; o.y += r4.y; o.z += r4.z; o.w += r4.w;
            }
            if (MODE == 1) {
                o.x = fmaxf(o.x, 0.f); o.y = fmaxf(o.y, 0.f);
                o.z = fmaxf(o.z, 0.f); o.w = fmaxf(o.w, 0.f);
            }
            int orow = REMAP ? (((row >> 2) << 3) + 4 + (row & 3)) : row;
            *(float4*)(C + orow*ldc + n0 + tx*4) = o;
        }
        __syncthreads();
    }
}

// in-place layernorm over 64 rows x 128 cols; 4 threads/row (consecutive lanes)
__device__ __forceinline__ void layernorm64(float* __restrict__ X,
                                            const float* __restrict__ w,
                                            const float* __restrict__ b, int tid)
{
    int r = tid >> 2, q = tid & 3;
    float* p = X + r*128 + q*32;
    float4 v[8];
    float s = 0.f, s2 = 0.f;
    #pragma unroll
    for (int i = 0; i < 8; i++) {
        v[i] = ((const float4*)p)[i];
        s  += v[i].x + v[i].y + v[i].z + v[i].w;
        s2 += v[i].x*v[i].x + v[i].y*v[i].y + v[i].z*v[i].z + v[i].w*v[i].w;
    }
    s  += __shfl_xor_sync(0xffffffffu, s, 1);
    s  += __shfl_xor_sync(0xffffffffu, s, 2);
    s2 += __shfl_xor_sync(0xffffffffu, s2, 1);
    s2 += __shfl_xor_sync(0xffffffffu, s2, 2);
    float mean = s * (1.f/128.f);
    float var  = s2 * (1.f/128.f) - mean*mean;
    float rstd = rsqrtf(var + 1e-5f);
    #pragma unroll
    for (int i = 0; i < 8; i++) {
        float4 wv = *(const float4*)(w + q*32 + i*4);
        float4 bv = *(const float4*)(b + q*32 + i*4);
        float4 o;
        o.x = (v[i].x - mean)*rstd*wv.x + bv.x;
        o.y = (v[i].y - mean)*rstd*wv.y + bv.y;
        o.z = (v[i].z - mean)*rstd*wv.z + bv.z;
        o.w = (v[i].w - mean)*rstd*wv.w + bv.w;
        ((float4*)p)[i] = o;
    }
}

__device__ __forceinline__ void load16(float* d, const float* __restrict__ s) {
    *(float4*)(d+0)  = *(const float4*)(s+0);
    *(float4*)(d+4)  = *(const float4*)(s+4);
    *(float4*)(d+8)  = *(const float4*)(s+8);
    *(float4*)(d+12) = *(const float4*)(s+12);
}

__global__ void __launch_bounds__(NTH, 1) edge_kernel(
    const float* __restrict__ xA, const float* __restrict__ xB,
    const int* __restrict__ eAB, const int* __restrict__ eBA,
    const float* __restrict__ bw_,  const float* __restrict__ bb_,
    const float* __restrict__ wi_,  const float* __restrict__ bi_,
    const float* __restrict__ wo_,  const float* __restrict__ bo_,
    const float* __restrict__ l1w_, const float* __restrict__ l1b_,
    const float* __restrict__ l2w_, const float* __restrict__ l2b_,
    const float* __restrict__ n1w_, const float* __restrict__ n1b_,
    const float* __restrict__ n2w_, const float* __restrict__ n2b_,
    float* __restrict__ out, int E0, int E1, int nBlk0, int NA)
{
    extern __shared__ float sm[];
    float* Xc = sm + S_XC;
    float* Qb = sm + S_Q;
    float* Kb = sm + S_K;
    float* Vb = sm + S_V;
    float* Ob = sm + S_O;
    float* Wb = sm + S_W;
    int*   sIdx = (int*)(sm + S_FLOATS);

    const int tid = threadIdx.x;
    const int rel = (blockIdx.x >= nBlk0) ? 1 : 0;
    const int blk = rel ? (blockIdx.x - nBlk0) : blockIdx.x;
    const int e0  = blk * EB;
    const int Ecur = rel ? E1 : E0;
    const int* eidx = rel ? eBA : eAB;
    const float* xs = rel ? xB : xA;
    const float* xd = rel ? xA : xB;
    float* outp = rel ? out : (out + (size_t)NA * 512);

    const float* bw  = bw_  + rel*16384; const float* bb  = bb_  + rel*128;
    const float* wi  = wi_  + rel*49152; const float* bi  = bi_  + rel*384;
    const float* wo  = wo_  + rel*16384; const float* bo  = bo_  + rel*128;
    const float* l1w = l1w_ + rel*8192;  const float* l1b = l1b_ + rel*64;
    const float* l2w = l2w_ + rel*8192;  const float* l2b = l2b_ + rel*128;
    const float* n1w = n1w_ + rel*128;   const float* n1b = n1b_ + rel*128;
    const float* n2w = n2w_ + rel*128;   const float* n2b = n2b_ + rel*128;

    if (tid < EB) {
        int e = e0 + tid;
        sIdx[tid]      = (e < Ecur) ? eidx[e] : 0;           // src
        sIdx[EB + tid] = (e < Ecur) ? eidx[Ecur + e] : 0;    // dst
    }
    __syncthreads();

    // gather: x_i -> Xc rows e*8+t (t<4); x_src -> Ob rows e*4+t
    #pragma unroll
    for (int it = 0; it < 4; it++) {
        int idx = it*NTH + tid;          // 1024 float4 units = 8 edges * 4 tok * 32
        int e  = idx >> 7;
        int r  = idx & 127;
        int t  = r >> 5, d4 = r & 31;
        int dst = sIdx[EB + e], src = sIdx[e];
        float4 vi = *(const float4*)(xd + ((size_t)dst*4 + t)*128 + d4*4);
        float4 vj = *(const float4*)(xs + ((size_t)src*4 + t)*128 + d4*4);
        *(float4*)(Xc + (e*8 + t)*128 + d4*4) = vi;
        *(float4*)(Ob + (e*4 + t)*128 + d4*4) = vj;
    }
    __syncthreads();

    // b_proj: Xc rows e*8+4+t = Ob(32x128) @ bw^T + bb
    gemm<128, 2, 0, true >(Ob, bw, bb, 128, Xc, 128, nullptr, Wb, tid);

    // qkv projections
    gemm<128, 4, 0, false>(Xc, wi,           bi,       128, Qb, 128, nullptr, Wb, tid);
    gemm<128, 4, 0, false>(Xc, wi + 16384,   bi + 128, 128, Kb, 128, nullptr, Wb, tid);
    gemm<128, 4, 0, false>(Xc, wi + 32768,   bi + 256, 128, Vb, 128, nullptr, Wb, tid);

    // attention: 64 (edge,head) groups x 4 subs, each sub handles 2 query rows
    {
        int g = tid >> 2, sub = tid & 3;
        int e = g >> 3, h = g & 7;
        const float* Qp = Qb + (e*8)*128 + h*16;
        const float* Kp = Kb + (e*8)*128 + h*16;
        const float* Vp = Vb + (e*8)*128 + h*16;
        float* Op = Ob + (e*8)*128 + h*16;
        int q0 = sub * 2;

        float qa[16], qc[16];
        load16(qa, Qp + q0*128);
        load16(qc, Qp + (q0+1)*128);

        float s0[8], s1[8];
        #pragma unroll
        for (int kk = 0; kk < 8; kk++) {
            float kr[16];
            load16(kr, Kp + kk*128);
            float d0 = 0.f, d1 = 0.f;
            #pragma unroll
            for (int c = 0; c < 16; c++) { d0 += qa[c]*kr[c]; d1 += qc[c]*kr[c]; }
            s0[kk] = d0 * 0.25f;   // 1/sqrt(16)
            s1[kk] = d1 * 0.25f;
        }
        float m0 = s0[0], m1 = s1[0];
        #pragma unroll
        for (int kk = 1; kk < 8; kk++) { m0 = fmaxf(m0, s0[kk]); m1 = fmaxf(m1, s1[kk]); }
        float sum0 = 0.f, sum1 = 0.f;
        #pragma unroll
        for (int kk = 0; kk < 8; kk++) {
            s0[kk] = __expf(s0[kk] - m0); sum0 += s0[kk];
            s1[kk] = __expf(s1[kk] - m1); sum1 += s1[kk];
        }
        float inv0 = 1.f / sum0, inv1 = 1.f / sum1;

        #pragma unroll
        for (int half = 0; half < 2; half++) {
            float o0[8] = {0,0,0,0,0,0,0,0};
            float o1[8] = {0,0,0,0,0,0,0,0};
            #pragma unroll
            for (int kk = 0; kk < 8; kk++) {
                float vr[8];
                *(float4*)(vr+0) = *(const float4*)(Vp + kk*128 + half*8);
                *(float4*)(vr+4) = *(const float4*)(Vp + kk*128 + half*8 + 4);
                #pragma unroll
                for (int c = 0; c < 8; c++) { o0[c] += s0[kk]*vr[c]; o1[c] += s1[kk]*vr[c]; }
            }
            #pragma unroll
            for (int c = 0; c < 8; c++) { o0[c] *= inv0; o1[c] *= inv1; }
            *(float4*)(Op + q0*128 + half*8)       = *(float4*)(o0+0);
            *(float4*)(Op + q0*128 + half*8 + 4)   = *(float4*)(o0+4);
            *(float4*)(Op + (q0+1)*128 + half*8)   = *(float4*)(o1+0);
            *(float4*)(Op + (q0+1)*128 + half*8+4) = *(float4*)(o1+4);
        }
    }
    __syncthreads();

    // attn out proj + residual -> X1 in Qb; LN1
    gemm<128, 4, 2, false>(Ob, wo, bo, 128, Qb, 128, Xc, Wb, tid);
    layernorm64(Qb, n1w, n1b, tid);
    __syncthreads();

    // FF: hidden = relu(X1 @ W1^T + b1) -> Kb (64x64); Y = X1 + hid @ W2^T + b2 -> Ob; LN2
    gemm<128, 4, 1, false>(Qb, l1w, l1b, 64,  Kb, 64,  nullptr, Wb, tid);
    gemm< 64, 4, 2, false>(Kb, l2w, l2b, 128, Ob, 128, Qb,      Wb, tid);
    layernorm64(Ob, n2w, n2b, tid);
    __syncthreads();

    // scatter tokens 0..3 of each edge into out sums
    #pragma unroll
    for (int it = 0; it < 16; it++) {
        int idx = it*NTH + tid;          // 4096 = 8 edges * 4 tok * 128
        int e = idx >> 9, r = idx & 511;
        if (e0 + e < Ecur) {
            int t = r >> 7, d = r & 127;
            atomicAdd(outp + ((size_t)sIdx[EB + e]*4 + t)*128 + d,
                      Ob[(e*8 + t)*128 + d]);
        }
    }
}

__global__ void zero_cnt_kernel(int n) {
    int i = blockIdx.x * blockDim.x + threadIdx.x;
    if (i < n) g_cnt[i] = 0;
}

__global__ void count_kernel(const int* __restrict__ eAB, const int* __restrict__ eBA,
                             int E0, int E1, int NA) {
    int i = blockIdx.x * blockDim.x + threadIdx.x;
    if (i < E0) {
        atomicAdd(&g_cnt[NA + eAB[E0 + i]], 1);          // A->B: dst is B node
    } else if (i < E0 + E1) {
        atomicAdd(&g_cnt[eBA[E1 + (i - E0)]], 1);        // B->A: dst is A node
    }
}

__global__ void finalize_kernel(float* __restrict__ out, int total) {
    int i = blockIdx.x * blockDim.x + threadIdx.x;
    if (i < total) {
        int node = i >> 9;               // 512 floats per node
        int c = g_cnt[node];
        out[i] *= 1.f / (float)(c > 0 ? c : 1);
    }
}

extern "C" void kernel_launch(void* const* d_in, const int* in_sizes, int n_in,
                              void* d_out, int out_size) {
    const float* xA  = (const float*)d_in[0];
    const float* xB  = (const float*)d_in[1];
    const int*   eAB = (const int*)  d_in[2];
    const int*   eBA = (const int*)  d_in[3];
    const float* bw  = (const float*)d_in[4];
    const float* bb  = (const float*)d_in[5];
    const float* wi  = (const float*)d_in[6];
    const float* bi  = (const float*)d_in[7];
    const float* wo  = (const float*)d_in[8];
    const float* bo  = (const float*)d_in[9];
    const float* l1w = (const float*)d_in[10];
    const float* l1b = (const float*)d_in[11];
    const float* l2w = (const float*)d_in[12];
    const float* l2b = (const float*)d_in[13];
    const float* n1w = (const float*)d_in[14];
    const float* n1b = (const float*)d_in[15];
    const float* n2w = (const float*)d_in[16];
    const float* n2b = (const float*)d_in[17];
    float* out = (float*)d_out;

    const int NA = in_sizes[0] / 512;
    const int NB = in_sizes[1] / 512;
    const int E0 = in_sizes[2] / 2;
    const int E1 = in_sizes[3] / 2;

    cudaFuncSetAttribute(edge_kernel, cudaFuncAttributeMaxDynamicSharedMemorySize,
                         (int)SMEM_BYTES);

    cudaMemsetAsync(d_out, 0, (size_t)out_size * sizeof(float));

    int nNodes = NA + NB;
    zero_cnt_kernel<<<(nNodes + 255) / 256, 256>>>(nNodes);
    count_kernel<<<(E0 + E1 + 255) / 256, 256>>>(eAB, eBA, E0, E1, NA);

    const int nBlk0 = (E0 + EB - 1) / EB;
    const int nBlk1 = (E1 + EB - 1) / EB;
    edge_kernel<<<nBlk0 + nBlk1, NTH, SMEM_BYTES>>>(
        xA, xB, eAB, eBA, bw, bb, wi, bi, wo, bo,
        l1w, l1b, l2w, l2b, n1w, n1b, n2w, n2b,
        out, E0, E1, nBlk0, NA);

    int total = nNodes * 512;
    finalize_kernel<<<(total + 255) / 256, 256>>>(out, total);
}